// round 1
// baseline (speedup 1.0000x reference)
#include <cuda_runtime.h>
#include <math.h>

#define NB 2
#define SL 2048
#define HDIM 2048
#define NHEAD 16
#define HD 128
#define MTOT (NB*SL)          // 4096
#define N3H (3*HDIM)          // 6144

#define CLIPV 8.0f
#define SM_SCALE 0.08838834764831845f   // 1/sqrt(128)

// ---- scratch (device globals; no allocation allowed) ----
__device__ float g_q[(size_t)NB*NHEAD*SL*HD];     // [B,NH,S,HD] 32MB
__device__ float g_k[(size_t)NB*NHEAD*SL*HD];
__device__ float g_v[(size_t)NB*NHEAD*SL*HD];
__device__ float g_ctx[(size_t)MTOT*HDIM];        // [B,S,H]   32MB

// ============================================================================
// NT SGEMM: C[M,N] = A[M,K](row) * B[N,K](row)^T.  128x128x8 tile, 256 thr,
// 8x8 per-thread microtile. MODE 0: plain store to C. MODE 1: clamp +- 8 and
// scatter into g_q/g_k/g_v with [B,NH,S,HD] layout.
// ============================================================================
template<int MODE>
__global__ __launch_bounds__(256, 2)
void sgemm_nt(const float* __restrict__ A, const float* __restrict__ Bm,
              float* __restrict__ C, int Ndim, int Kdim)
{
    __shared__ float As[8][132];
    __shared__ float Bs[8][132];

    const int tid = threadIdx.x;
    const int tx = tid & 15;
    const int ty = tid >> 4;
    const int lrow = tid >> 1;
    const int lk4  = (tid & 1) * 4;

    const float* Ap = A  + ((size_t)(blockIdx.y*128 + lrow))*Kdim + lk4;
    const float* Bp = Bm + ((size_t)(blockIdx.x*128 + lrow))*Kdim + lk4;

    float acc[8][8];
#pragma unroll
    for (int i = 0; i < 8; i++)
#pragma unroll
        for (int j = 0; j < 8; j++) acc[i][j] = 0.f;

    float4 av = *(const float4*)Ap;
    float4 bv = *(const float4*)Bp;

    for (int kt = 0; kt < Kdim; kt += 8) {
        __syncthreads();
        As[lk4+0][lrow] = av.x; As[lk4+1][lrow] = av.y;
        As[lk4+2][lrow] = av.z; As[lk4+3][lrow] = av.w;
        Bs[lk4+0][lrow] = bv.x; Bs[lk4+1][lrow] = bv.y;
        Bs[lk4+2][lrow] = bv.z; Bs[lk4+3][lrow] = bv.w;
        __syncthreads();
        if (kt + 8 < Kdim) {
            av = *(const float4*)(Ap + kt + 8);
            bv = *(const float4*)(Bp + kt + 8);
        }
#pragma unroll
        for (int k = 0; k < 8; k++) {
            float a[8], b[8];
            *(float4*)&a[0] = *(const float4*)&As[k][ty*8];
            *(float4*)&a[4] = *(const float4*)&As[k][ty*8+4];
            *(float4*)&b[0] = *(const float4*)&Bs[k][tx*8];
            *(float4*)&b[4] = *(const float4*)&Bs[k][tx*8+4];
#pragma unroll
            for (int i = 0; i < 8; i++)
#pragma unroll
                for (int j = 0; j < 8; j++)
                    acc[i][j] = fmaf(a[i], b[j], acc[i][j]);
        }
    }

    const int m0 = blockIdx.y*128 + ty*8;
    const int n0 = blockIdx.x*128 + tx*8;

    if (MODE == 0) {
#pragma unroll
        for (int i = 0; i < 8; i++) {
            float* dst = C + (size_t)(m0+i)*Ndim + n0;
            *(float4*)dst     = *(float4*)&acc[i][0];
            *(float4*)(dst+4) = *(float4*)&acc[i][4];
        }
    } else {
        // n0 is 8-aligned inside a 128-block -> part/h/d0 constant per thread
        const int part = n0 >> 11;          // 0:Q 1:K 2:V
        const int c    = n0 & 2047;
        const int hh   = c >> 7;
        const int d0   = c & 127;
        float* base = (part == 0) ? g_q : (part == 1) ? g_k : g_v;
#pragma unroll
        for (int i = 0; i < 8; i++) {
            const int m = m0 + i;
            const int bb = m >> 11;         // m / S
            const int ss = m & 2047;        // m % S
            float* dst = base + ((((size_t)bb*NHEAD) + hh)*SL + ss)*HD + d0;
            float v[8];
#pragma unroll
            for (int j = 0; j < 8; j++)
                v[j] = fminf(fmaxf(acc[i][j], -CLIPV), CLIPV);
            *(float4*)dst     = *(float4*)&v[0];
            *(float4*)(dst+4) = *(float4*)&v[4];
        }
    }
}

// ============================================================================
// Flash attention (fp32 SIMT). Block: 64 queries, iterate 64-key tiles up to
// the causal diagonal. 256 threads = 16x16; thread (ty,tx) owns score rows
// q = ty*4+i and keys kl = tx + 16*j (remap keeps all smem reads conflict-free
// at stride 129). O accumulated in regs: 4 queries x 8 dims (cols tx*8..+7).
// ============================================================================
#define ATT_SMEM_FLOATS (64*129 + 64*129 + 64*132 + 64*65)
#define ATT_SMEM_BYTES  (ATT_SMEM_FLOATS*4)

__global__ __launch_bounds__(256, 1)
void attn_kernel(const float* __restrict__ bias)
{
    extern __shared__ float sm[];
    float* Qs = sm;                         // [64][129]
    float* Ks = sm + 64*129;                // [64][129]
    float* Vs = sm + 2*64*129;              // [64][132]
    float* Ps = sm + 2*64*129 + 64*132;     // [64][65]

    const int qb = blockIdx.x;
    const int hh = blockIdx.y;
    const int bb = blockIdx.z;
    const int tid = threadIdx.x;
    const int tx = tid & 15;
    const int ty = tid >> 4;

    const size_t bh = (size_t)bb*NHEAD + hh;
    const float* Qg = g_q + bh*SL*HD + (size_t)qb*64*HD;
    const float* Kg = g_k + bh*SL*HD;
    const float* Vg = g_v + bh*SL*HD;
    const float* biasg = bias + ((size_t)hh*SL + (size_t)qb*64)*SL;

    // load Q tile
    for (int i = tid; i < 64*32; i += 256) {
        int r = i >> 5, c4 = (i & 31) << 2;
        float4 v = *(const float4*)(Qg + r*HD + c4);
        float* p = Qs + r*129 + c4;
        p[0]=v.x; p[1]=v.y; p[2]=v.z; p[3]=v.w;
    }

    float o[4][8];
    float mr[4], lr[4];
#pragma unroll
    for (int i = 0; i < 4; i++) {
        mr[i] = -INFINITY; lr[i] = 0.f;
#pragma unroll
        for (int j = 0; j < 8; j++) o[i][j] = 0.f;
    }

    for (int kb = 0; kb <= qb; kb++) {
        __syncthreads();   // prev PV done before K/V/Ps overwrite
        const float* Kt = Kg + (size_t)kb*64*HD;
        const float* Vt = Vg + (size_t)kb*64*HD;
        for (int i = tid; i < 64*32; i += 256) {
            int r = i >> 5, c4 = (i & 31) << 2;
            float4 kv = *(const float4*)(Kt + r*HD + c4);
            float* p = Ks + r*129 + c4;
            p[0]=kv.x; p[1]=kv.y; p[2]=kv.z; p[3]=kv.w;
            float4 vv = *(const float4*)(Vt + r*HD + c4);
            *(float4*)(Vs + r*132 + c4) = vv;
        }
        __syncthreads();

        float s[4][4];
#pragma unroll
        for (int i = 0; i < 4; i++)
#pragma unroll
            for (int j = 0; j < 4; j++) s[i][j] = 0.f;

#pragma unroll 4
        for (int d = 0; d < HD; d++) {
            float a[4], b[4];
#pragma unroll
            for (int i = 0; i < 4; i++) a[i] = Qs[(ty*4+i)*129 + d];
#pragma unroll
            for (int j = 0; j < 4; j++) b[j] = Ks[(tx + 16*j)*129 + d];
#pragma unroll
            for (int i = 0; i < 4; i++)
#pragma unroll
                for (int j = 0; j < 4; j++)
                    s[i][j] = fmaf(a[i], b[j], s[i][j]);
        }

        const bool diag = (kb == qb);
#pragma unroll
        for (int i = 0; i < 4; i++) {
            const int ql = ty*4 + i;
            const float* brow = biasg + (size_t)ql*SL + (size_t)kb*64;
            float rm = -INFINITY;
#pragma unroll
            for (int j = 0; j < 4; j++) {
                const int kl = tx + 16*j;
                float v = fmaf(s[i][j], SM_SCALE, brow[kl]);
                if (diag && kl > ql) v = -INFINITY;
                s[i][j] = v;
                rm = fmaxf(rm, v);
            }
#pragma unroll
            for (int off = 8; off; off >>= 1)
                rm = fmaxf(rm, __shfl_xor_sync(0xffffffffu, rm, off));
            const float mn = fmaxf(mr[i], rm);
            const float corr = __expf(mr[i] - mn);
            mr[i] = mn;
            float rs = 0.f;
#pragma unroll
            for (int j = 0; j < 4; j++) {
                float p = __expf(s[i][j] - mn);
                s[i][j] = p;
                rs += p;
            }
#pragma unroll
            for (int off = 8; off; off >>= 1)
                rs += __shfl_xor_sync(0xffffffffu, rs, off);
            lr[i] = lr[i]*corr + rs;
#pragma unroll
            for (int jd = 0; jd < 8; jd++) o[i][jd] *= corr;
#pragma unroll
            for (int j = 0; j < 4; j++)
                Ps[ql*65 + tx + 16*j] = s[i][j];
        }
        __syncthreads();

#pragma unroll 2
        for (int jj = 0; jj < 64; jj++) {
            float p0 = Ps[(ty*4+0)*65 + jj];
            float p1 = Ps[(ty*4+1)*65 + jj];
            float p2 = Ps[(ty*4+2)*65 + jj];
            float p3 = Ps[(ty*4+3)*65 + jj];
            float4 v0 = *(const float4*)(Vs + jj*132 + tx*8);
            float4 v1 = *(const float4*)(Vs + jj*132 + tx*8 + 4);
            float vv[8] = {v0.x, v0.y, v0.z, v0.w, v1.x, v1.y, v1.z, v1.w};
#pragma unroll
            for (int jd = 0; jd < 8; jd++) {
                o[0][jd] = fmaf(p0, vv[jd], o[0][jd]);
                o[1][jd] = fmaf(p1, vv[jd], o[1][jd]);
                o[2][jd] = fmaf(p2, vv[jd], o[2][jd]);
                o[3][jd] = fmaf(p3, vv[jd], o[3][jd]);
            }
        }
    }

    // epilogue: normalize, write ctx in [B,S,H] layout
#pragma unroll
    for (int i = 0; i < 4; i++) {
        const int q = qb*64 + ty*4 + i;
        const float inv = 1.0f / lr[i];
        float* dst = g_ctx + (((size_t)bb*SL + q)*NHEAD + hh)*HD + tx*8;
        float4 r0 = make_float4(o[i][0]*inv, o[i][1]*inv, o[i][2]*inv, o[i][3]*inv);
        float4 r1 = make_float4(o[i][4]*inv, o[i][5]*inv, o[i][6]*inv, o[i][7]*inv);
        *(float4*)dst     = r0;
        *(float4*)(dst+4) = r1;
    }
}

// ============================================================================
extern "C" void kernel_launch(void* const* d_in, const int* in_sizes, int n_in,
                              void* d_out, int out_size)
{
    const float* hidden = (const float*)d_in[0];   // [B,S,H]
    const float* bias   = (const float*)d_in[1];   // [NH,S,S]
    // d_in[2] attention_mask: deterministic causal, applied analytically
    const float* Wqkv   = (const float*)d_in[3];   // [3H,H]
    const float* Wout   = (const float*)d_in[4];   // [H,H]
    float* out = (float*)d_out;

    cudaFuncSetAttribute(attn_kernel,
                         cudaFuncAttributeMaxDynamicSharedMemorySize,
                         ATT_SMEM_BYTES);

    void* ctx_ptr = nullptr;
    cudaGetSymbolAddress(&ctx_ptr, g_ctx);

    // 1) QKV projection + clamp + head-split scatter
    sgemm_nt<1><<<dim3(N3H/128, MTOT/128), 256>>>(hidden, Wqkv, nullptr, N3H, HDIM);

    // 2) attention (flash, causal, + position bias)
    attn_kernel<<<dim3(SL/64, NHEAD, NB), 256, ATT_SMEM_BYTES>>>(bias);

    // 3) output projection
    sgemm_nt<0><<<dim3(HDIM/128, MTOT/128), 256>>>((const float*)ctx_ptr, Wout,
                                                   out, HDIM, HDIM);
}

// round 2
// speedup vs baseline: 1.1817x; 1.1817x over previous
#include <cuda_runtime.h>
#include <math.h>
#include <stdint.h>

#define NB 2
#define SL 2048
#define HDIM 2048
#define NHEAD 16
#define HD 128
#define MTOT (NB*SL)          // 4096
#define N3H (3*HDIM)          // 6144

#define CLIPV 8.0f
#define SM_SCALE 0.08838834764831845f   // 1/sqrt(128)

// ---- scratch (device globals; no allocation allowed) ----
__device__ float g_q[(size_t)NB*NHEAD*SL*HD];     // [B,NH,S,HD] 32MB
__device__ float g_k[(size_t)NB*NHEAD*SL*HD];
__device__ float g_v[(size_t)NB*NHEAD*SL*HD];
__device__ float g_ctx[(size_t)MTOT*HDIM];        // [B,S,H]   32MB

// ============================================================================
// tf32 tensor-core NT GEMM: C[M,N] = A[M,K](row) * B[N,K](row)^T.
// CTA tile 128x128x32, 256 threads = 8 warps (4 along M x 2 along N),
// warp tile 32x64 = 2x8 mma.m16n8k8 tiles, fp32 accumulate.
// Smem row stride 36 floats => fragment LDS addr = 4*grp + tig (mod 32),
// conflict-free. Inputs rounded to tf32 once on the smem-fill path.
// MODE 0: plain store. MODE 1: clamp +-8, scatter to g_q/g_k/g_v [B,NH,S,HD].
// ============================================================================
__device__ __forceinline__ uint32_t f2tf32(float x) {
    uint32_t r;
    asm("cvt.rna.tf32.f32 %0, %1;" : "=r"(r) : "f"(x));
    return r;
}

template<int MODE>
__global__ __launch_bounds__(256)
void mma_gemm_nt(const float* __restrict__ A, const float* __restrict__ Bm,
                 float* __restrict__ C, int Ndim, int Kdim)
{
    __shared__ uint32_t As[128][36];
    __shared__ uint32_t Bs[128][36];

    const int tid  = threadIdx.x;
    const int w    = tid >> 5;
    const int lane = tid & 31;
    const int grp  = lane >> 2;    // 0..7
    const int tig  = lane & 3;     // 0..3
    const int wm   = w & 3;        // warp row (4)
    const int wn   = w >> 2;       // warp col (2)

    const int k4 = (tid & 7) * 4;  // 0,4,..,28
    const int mb = tid >> 3;       // 0..31

    const float* Ag = A  + (size_t)(blockIdx.y*128 + mb)*Kdim + k4;
    const float* Bg = Bm + (size_t)(blockIdx.x*128 + mb)*Kdim + k4;

    float acc[2][8][4];
#pragma unroll
    for (int mt = 0; mt < 2; mt++)
#pragma unroll
        for (int nt = 0; nt < 8; nt++)
#pragma unroll
            for (int r = 0; r < 4; r++) acc[mt][nt][r] = 0.f;

    for (int kt = 0; kt < Kdim; kt += 32) {
        __syncthreads();
#pragma unroll
        for (int i = 0; i < 4; i++) {
            float4 a = *(const float4*)(Ag + (size_t)(i*32)*Kdim + kt);
            uint32_t* pa = &As[mb + i*32][k4];
            pa[0] = f2tf32(a.x); pa[1] = f2tf32(a.y);
            pa[2] = f2tf32(a.z); pa[3] = f2tf32(a.w);
            float4 b = *(const float4*)(Bg + (size_t)(i*32)*Kdim + kt);
            uint32_t* pb = &Bs[mb + i*32][k4];
            pb[0] = f2tf32(b.x); pb[1] = f2tf32(b.y);
            pb[2] = f2tf32(b.z); pb[3] = f2tf32(b.w);
        }
        __syncthreads();

#pragma unroll
        for (int kk = 0; kk < 32; kk += 8) {
            uint32_t af[2][4], bf[8][2];
#pragma unroll
            for (int mt = 0; mt < 2; mt++) {
                const int r = wm*32 + mt*16 + grp;
                af[mt][0] = As[r    ][kk + tig];
                af[mt][1] = As[r + 8][kk + tig];
                af[mt][2] = As[r    ][kk + tig + 4];
                af[mt][3] = As[r + 8][kk + tig + 4];
            }
#pragma unroll
            for (int nt = 0; nt < 8; nt++) {
                const int r = wn*64 + nt*8 + grp;
                bf[nt][0] = Bs[r][kk + tig];
                bf[nt][1] = Bs[r][kk + tig + 4];
            }
#pragma unroll
            for (int mt = 0; mt < 2; mt++)
#pragma unroll
                for (int nt = 0; nt < 8; nt++) {
                    asm volatile(
                        "mma.sync.aligned.m16n8k8.row.col.f32.tf32.tf32.f32 "
                        "{%0,%1,%2,%3}, {%4,%5,%6,%7}, {%8,%9}, {%0,%1,%2,%3};"
                        : "+f"(acc[mt][nt][0]), "+f"(acc[mt][nt][1]),
                          "+f"(acc[mt][nt][2]), "+f"(acc[mt][nt][3])
                        : "r"(af[mt][0]), "r"(af[mt][1]),
                          "r"(af[mt][2]), "r"(af[mt][3]),
                          "r"(bf[nt][0]), "r"(bf[nt][1]));
                }
        }
    }

    // ---- epilogue ----
    if (MODE == 0) {
#pragma unroll
        for (int mt = 0; mt < 2; mt++) {
            const int r0 = blockIdx.y*128 + wm*32 + mt*16 + grp;
#pragma unroll
            for (int nt = 0; nt < 8; nt++) {
                const int n = blockIdx.x*128 + wn*64 + nt*8 + 2*tig;
                *(float2*)(C + (size_t)r0*Ndim + n) =
                    make_float2(acc[mt][nt][0], acc[mt][nt][1]);
                *(float2*)(C + (size_t)(r0+8)*Ndim + n) =
                    make_float2(acc[mt][nt][2], acc[mt][nt][3]);
            }
        }
    } else {
        // block's 128-wide n-range lies inside one (part, head) region
        const int nblk = blockIdx.x*128;
        const int part = nblk >> 11;           // 0:Q 1:K 2:V
        const int hh   = (nblk & 2047) >> 7;
        float* base = (part == 0) ? g_q : (part == 1) ? g_k : g_v;
#pragma unroll
        for (int mt = 0; mt < 2; mt++) {
            const int m0 = blockIdx.y*128 + wm*32 + mt*16 + grp;
#pragma unroll
            for (int rr = 0; rr < 2; rr++) {
                const int m  = m0 + rr*8;
                const int bb = m >> 11;
                const int ss = m & 2047;
                float* row = base + ((((size_t)bb*NHEAD) + hh)*SL + ss)*HD;
#pragma unroll
                for (int nt = 0; nt < 8; nt++) {
                    const int d = wn*64 + nt*8 + 2*tig;
                    float v0 = fminf(fmaxf(acc[mt][nt][rr*2+0], -CLIPV), CLIPV);
                    float v1 = fminf(fmaxf(acc[mt][nt][rr*2+1], -CLIPV), CLIPV);
                    *(float2*)(row + d) = make_float2(v0, v1);
                }
            }
        }
    }
}

// ============================================================================
// Flash attention (fp32 SIMT), unchanged from R1.
// ============================================================================
#define ATT_SMEM_FLOATS (64*129 + 64*129 + 64*132 + 64*65)
#define ATT_SMEM_BYTES  (ATT_SMEM_FLOATS*4)

__global__ __launch_bounds__(256, 1)
void attn_kernel(const float* __restrict__ bias)
{
    extern __shared__ float sm[];
    float* Qs = sm;                         // [64][129]
    float* Ks = sm + 64*129;                // [64][129]
    float* Vs = sm + 2*64*129;              // [64][132]
    float* Ps = sm + 2*64*129 + 64*132;     // [64][65]

    const int qb = blockIdx.x;
    const int hh = blockIdx.y;
    const int bb = blockIdx.z;
    const int tid = threadIdx.x;
    const int tx = tid & 15;
    const int ty = tid >> 4;

    const size_t bh = (size_t)bb*NHEAD + hh;
    const float* Qg = g_q + bh*SL*HD + (size_t)qb*64*HD;
    const float* Kg = g_k + bh*SL*HD;
    const float* Vg = g_v + bh*SL*HD;
    const float* biasg = bias + ((size_t)hh*SL + (size_t)qb*64)*SL;

    for (int i = tid; i < 64*32; i += 256) {
        int r = i >> 5, c4 = (i & 31) << 2;
        float4 v = *(const float4*)(Qg + r*HD + c4);
        float* p = Qs + r*129 + c4;
        p[0]=v.x; p[1]=v.y; p[2]=v.z; p[3]=v.w;
    }

    float o[4][8];
    float mr[4], lr[4];
#pragma unroll
    for (int i = 0; i < 4; i++) {
        mr[i] = -INFINITY; lr[i] = 0.f;
#pragma unroll
        for (int j = 0; j < 8; j++) o[i][j] = 0.f;
    }

    for (int kb = 0; kb <= qb; kb++) {
        __syncthreads();
        const float* Kt = Kg + (size_t)kb*64*HD;
        const float* Vt = Vg + (size_t)kb*64*HD;
        for (int i = tid; i < 64*32; i += 256) {
            int r = i >> 5, c4 = (i & 31) << 2;
            float4 kv = *(const float4*)(Kt + r*HD + c4);
            float* p = Ks + r*129 + c4;
            p[0]=kv.x; p[1]=kv.y; p[2]=kv.z; p[3]=kv.w;
            float4 vv = *(const float4*)(Vt + r*HD + c4);
            *(float4*)(Vs + r*132 + c4) = vv;
        }
        __syncthreads();

        float s[4][4];
#pragma unroll
        for (int i = 0; i < 4; i++)
#pragma unroll
            for (int j = 0; j < 4; j++) s[i][j] = 0.f;

#pragma unroll 4
        for (int d = 0; d < HD; d++) {
            float a[4], b[4];
#pragma unroll
            for (int i = 0; i < 4; i++) a[i] = Qs[(ty*4+i)*129 + d];
#pragma unroll
            for (int j = 0; j < 4; j++) b[j] = Ks[(tx + 16*j)*129 + d];
#pragma unroll
            for (int i = 0; i < 4; i++)
#pragma unroll
                for (int j = 0; j < 4; j++)
                    s[i][j] = fmaf(a[i], b[j], s[i][j]);
        }

        const bool diag = (kb == qb);
#pragma unroll
        for (int i = 0; i < 4; i++) {
            const int ql = ty*4 + i;
            const float* brow = biasg + (size_t)ql*SL + (size_t)kb*64;
            float rm = -INFINITY;
#pragma unroll
            for (int j = 0; j < 4; j++) {
                const int kl = tx + 16*j;
                float v = fmaf(s[i][j], SM_SCALE, brow[kl]);
                if (diag && kl > ql) v = -INFINITY;
                s[i][j] = v;
                rm = fmaxf(rm, v);
            }
#pragma unroll
            for (int off = 8; off; off >>= 1)
                rm = fmaxf(rm, __shfl_xor_sync(0xffffffffu, rm, off));
            const float mn = fmaxf(mr[i], rm);
            const float corr = __expf(mr[i] - mn);
            mr[i] = mn;
            float rs = 0.f;
#pragma unroll
            for (int j = 0; j < 4; j++) {
                float p = __expf(s[i][j] - mn);
                s[i][j] = p;
                rs += p;
            }
#pragma unroll
            for (int off = 8; off; off >>= 1)
                rs += __shfl_xor_sync(0xffffffffu, rs, off);
            lr[i] = lr[i]*corr + rs;
#pragma unroll
            for (int jd = 0; jd < 8; jd++) o[i][jd] *= corr;
#pragma unroll
            for (int j = 0; j < 4; j++)
                Ps[ql*65 + tx + 16*j] = s[i][j];
        }
        __syncthreads();

#pragma unroll 2
        for (int jj = 0; jj < 64; jj++) {
            float p0 = Ps[(ty*4+0)*65 + jj];
            float p1 = Ps[(ty*4+1)*65 + jj];
            float p2 = Ps[(ty*4+2)*65 + jj];
            float p3 = Ps[(ty*4+3)*65 + jj];
            float4 v0 = *(const float4*)(Vs + jj*132 + tx*8);
            float4 v1 = *(const float4*)(Vs + jj*132 + tx*8 + 4);
            float vv[8] = {v0.x, v0.y, v0.z, v0.w, v1.x, v1.y, v1.z, v1.w};
#pragma unroll
            for (int jd = 0; jd < 8; jd++) {
                o[0][jd] = fmaf(p0, vv[jd], o[0][jd]);
                o[1][jd] = fmaf(p1, vv[jd], o[1][jd]);
                o[2][jd] = fmaf(p2, vv[jd], o[2][jd]);
                o[3][jd] = fmaf(p3, vv[jd], o[3][jd]);
            }
        }
    }

#pragma unroll
    for (int i = 0; i < 4; i++) {
        const int q = qb*64 + ty*4 + i;
        const float inv = 1.0f / lr[i];
        float* dst = g_ctx + (((size_t)bb*SL + q)*NHEAD + hh)*HD + tx*8;
        float4 r0 = make_float4(o[i][0]*inv, o[i][1]*inv, o[i][2]*inv, o[i][3]*inv);
        float4 r1 = make_float4(o[i][4]*inv, o[i][5]*inv, o[i][6]*inv, o[i][7]*inv);
        *(float4*)dst     = r0;
        *(float4*)(dst+4) = r1;
    }
}

// ============================================================================
extern "C" void kernel_launch(void* const* d_in, const int* in_sizes, int n_in,
                              void* d_out, int out_size)
{
    const float* hidden = (const float*)d_in[0];   // [B,S,H]
    const float* bias   = (const float*)d_in[1];   // [NH,S,S]
    // d_in[2] attention_mask: deterministic causal, applied analytically
    const float* Wqkv   = (const float*)d_in[3];   // [3H,H]
    const float* Wout   = (const float*)d_in[4];   // [H,H]
    float* out = (float*)d_out;

    cudaFuncSetAttribute(attn_kernel,
                         cudaFuncAttributeMaxDynamicSharedMemorySize,
                         ATT_SMEM_BYTES);

    void* ctx_ptr = nullptr;
    cudaGetSymbolAddress(&ctx_ptr, g_ctx);

    // 1) QKV projection + clamp + head-split scatter (tf32 tensor cores)
    mma_gemm_nt<1><<<dim3(N3H/128, MTOT/128), 256>>>(hidden, Wqkv, nullptr, N3H, HDIM);

    // 2) attention (flash, causal, + position bias)
    attn_kernel<<<dim3(SL/64, NHEAD, NB), 256, ATT_SMEM_BYTES>>>(bias);

    // 3) output projection (tf32 tensor cores)
    mma_gemm_nt<0><<<dim3(HDIM/128, MTOT/128), 256>>>((const float*)ctx_ptr, Wout,
                                                      out, HDIM, HDIM);
}

// round 3
// speedup vs baseline: 2.8328x; 2.3972x over previous
#include <cuda_runtime.h>
#include <math.h>
#include <stdint.h>

#define NB 2
#define SL 2048
#define HDIM 2048
#define NHEAD 16
#define HD 128
#define MTOT (NB*SL)          // 4096
#define N3H (3*HDIM)          // 6144

#define CLIPV 8.0f
#define SM_SCALE 0.08838834764831845f   // 1/sqrt(128)

// ---- scratch (device globals; no allocation allowed) ----
__device__ float g_q[(size_t)NB*NHEAD*SL*HD];     // [B,NH,S,HD] 32MB
__device__ float g_k[(size_t)NB*NHEAD*SL*HD];
__device__ float g_v[(size_t)NB*NHEAD*SL*HD];
__device__ float g_ctx[(size_t)MTOT*HDIM];        // [B,S,H]   32MB

__device__ __forceinline__ uint32_t f2tf32(float x) {
    uint32_t r;
    asm("cvt.rna.tf32.f32 %0, %1;" : "=r"(r) : "f"(x));
    return r;
}

__device__ __forceinline__ void mma16n8k8(float* d, const uint32_t* a,
                                          const uint32_t* b) {
    asm volatile(
        "mma.sync.aligned.m16n8k8.row.col.f32.tf32.tf32.f32 "
        "{%0,%1,%2,%3}, {%4,%5,%6,%7}, {%8,%9}, {%0,%1,%2,%3};"
        : "+f"(d[0]), "+f"(d[1]), "+f"(d[2]), "+f"(d[3])
        : "r"(a[0]), "r"(a[1]), "r"(a[2]), "r"(a[3]),
          "r"(b[0]), "r"(b[1]));
}

// ============================================================================
// tf32 tensor-core NT GEMM (unchanged from R2).
// ============================================================================
template<int MODE>
__global__ __launch_bounds__(256)
void mma_gemm_nt(const float* __restrict__ A, const float* __restrict__ Bm,
                 float* __restrict__ C, int Ndim, int Kdim)
{
    __shared__ uint32_t As[128][36];
    __shared__ uint32_t Bs[128][36];

    const int tid  = threadIdx.x;
    const int w    = tid >> 5;
    const int lane = tid & 31;
    const int grp  = lane >> 2;
    const int tig  = lane & 3;
    const int wm   = w & 3;
    const int wn   = w >> 2;

    const int k4 = (tid & 7) * 4;
    const int mb = tid >> 3;

    const float* Ag = A  + (size_t)(blockIdx.y*128 + mb)*Kdim + k4;
    const float* Bg = Bm + (size_t)(blockIdx.x*128 + mb)*Kdim + k4;

    float acc[2][8][4];
#pragma unroll
    for (int mt = 0; mt < 2; mt++)
#pragma unroll
        for (int nt = 0; nt < 8; nt++)
#pragma unroll
            for (int r = 0; r < 4; r++) acc[mt][nt][r] = 0.f;

    for (int kt = 0; kt < Kdim; kt += 32) {
        __syncthreads();
#pragma unroll
        for (int i = 0; i < 4; i++) {
            float4 a = *(const float4*)(Ag + (size_t)(i*32)*Kdim + kt);
            uint32_t* pa = &As[mb + i*32][k4];
            pa[0] = f2tf32(a.x); pa[1] = f2tf32(a.y);
            pa[2] = f2tf32(a.z); pa[3] = f2tf32(a.w);
            float4 b = *(const float4*)(Bg + (size_t)(i*32)*Kdim + kt);
            uint32_t* pb = &Bs[mb + i*32][k4];
            pb[0] = f2tf32(b.x); pb[1] = f2tf32(b.y);
            pb[2] = f2tf32(b.z); pb[3] = f2tf32(b.w);
        }
        __syncthreads();

#pragma unroll
        for (int kk = 0; kk < 32; kk += 8) {
            uint32_t af[2][4], bf[8][2];
#pragma unroll
            for (int mt = 0; mt < 2; mt++) {
                const int r = wm*32 + mt*16 + grp;
                af[mt][0] = As[r    ][kk + tig];
                af[mt][1] = As[r + 8][kk + tig];
                af[mt][2] = As[r    ][kk + tig + 4];
                af[mt][3] = As[r + 8][kk + tig + 4];
            }
#pragma unroll
            for (int nt = 0; nt < 8; nt++) {
                const int r = wn*64 + nt*8 + grp;
                bf[nt][0] = Bs[r][kk + tig];
                bf[nt][1] = Bs[r][kk + tig + 4];
            }
#pragma unroll
            for (int mt = 0; mt < 2; mt++)
#pragma unroll
                for (int nt = 0; nt < 8; nt++)
                    mma16n8k8(acc[mt][nt], af[mt], bf[nt]);
        }
    }

    if (MODE == 0) {
#pragma unroll
        for (int mt = 0; mt < 2; mt++) {
            const int r0 = blockIdx.y*128 + wm*32 + mt*16 + grp;
#pragma unroll
            for (int nt = 0; nt < 8; nt++) {
                const int n = blockIdx.x*128 + wn*64 + nt*8 + 2*tig;
                *(float2*)(C + (size_t)r0*Ndim + n) =
                    make_float2(acc[mt][nt][0], acc[mt][nt][1]);
                *(float2*)(C + (size_t)(r0+8)*Ndim + n) =
                    make_float2(acc[mt][nt][2], acc[mt][nt][3]);
            }
        }
    } else {
        const int nblk = blockIdx.x*128;
        const int part = nblk >> 11;
        const int hh   = (nblk & 2047) >> 7;
        float* base = (part == 0) ? g_q : (part == 1) ? g_k : g_v;
#pragma unroll
        for (int mt = 0; mt < 2; mt++) {
            const int m0 = blockIdx.y*128 + wm*32 + mt*16 + grp;
#pragma unroll
            for (int rr = 0; rr < 2; rr++) {
                const int m  = m0 + rr*8;
                const int bb = m >> 11;
                const int ss = m & 2047;
                float* row = base + ((((size_t)bb*NHEAD) + hh)*SL + ss)*HD;
#pragma unroll
                for (int nt = 0; nt < 8; nt++) {
                    const int d = wn*64 + nt*8 + 2*tig;
                    float v0 = fminf(fmaxf(acc[mt][nt][rr*2+0], -CLIPV), CLIPV);
                    float v1 = fminf(fmaxf(acc[mt][nt][rr*2+1], -CLIPV), CLIPV);
                    *(float2*)(row + d) = make_float2(v0, v1);
                }
            }
        }
    }
}

// ============================================================================
// Tensor-core flash attention (tf32 mma), BM=128 queries, BN=64 keys, 8 warps.
// Smem strides all ≡ 4 (mod 32) so every fragment LDS hits bank 4*grp+tig+const
// -> conflict-free. V stored transposed [dim][key] for PV B-fragments.
// P staged per-warp (own 16 rows only) -> __syncwarp, no block barrier.
// ============================================================================
#define QS_STRIDE 132
#define VS_STRIDE 68
#define PS_STRIDE 68
#define ATT_U32   (128*QS_STRIDE + 64*QS_STRIDE + 128*VS_STRIDE + 128*PS_STRIDE)
#define ATT_BYTES (ATT_U32*4)

__global__ __launch_bounds__(256, 1)
void attn_mma(const float* __restrict__ bias)
{
    extern __shared__ uint32_t sm[];
    uint32_t* Qs = sm;                          // [128][132] tf32, pre-scaled
    uint32_t* Ks = Qs + 128*QS_STRIDE;          // [64][132]  tf32  [key][d]
    uint32_t* Vt = Ks + 64*QS_STRIDE;           // [128][68]  tf32  [d][key]
    uint32_t* Ps = Vt + 128*VS_STRIDE;          // [128][68]  tf32  [q][key]

    const int qb = blockIdx.x;
    const int hh = blockIdx.y;
    const int bb = blockIdx.z;
    const int tid  = threadIdx.x;
    const int w    = tid >> 5;
    const int lane = tid & 31;
    const int grp  = lane >> 2;
    const int tig  = lane & 3;
    const int rbase = w*16;

    const size_t bhs = ((size_t)bb*NHEAD + hh)*SL;
    const float* Qg = g_q + (bhs + (size_t)qb*128)*HD;
    const float* Kg = g_k + bhs*HD;
    const float* Vg = g_v + bhs*HD;

    // Q tile: 128x128, pre-scaled, tf32
    for (int i = tid; i < 128*32; i += 256) {
        int r = i >> 5, c4 = (i & 31) << 2;
        float4 v = *(const float4*)(Qg + (size_t)r*HD + c4);
        uint32_t* p = Qs + r*QS_STRIDE + c4;
        p[0] = f2tf32(v.x*SM_SCALE); p[1] = f2tf32(v.y*SM_SCALE);
        p[2] = f2tf32(v.z*SM_SCALE); p[3] = f2tf32(v.w*SM_SCALE);
    }

    float o[16][4];
#pragma unroll
    for (int nt = 0; nt < 16; nt++)
#pragma unroll
        for (int r = 0; r < 4; r++) o[nt][r] = 0.f;
    float mr0 = -INFINITY, mr1 = -INFINITY, lr0 = 0.f, lr1 = 0.f;

    const int rg0 = qb*128 + rbase + grp;     // this thread's first query row
    const int warp_rmax = qb*128 + rbase + 15;
    const int kb_max = 2*qb + 1;

    for (int kb = 0; kb <= kb_max; kb++) {
        __syncthreads();   // previous iteration's PV reads done
        const float* Kt = Kg + (size_t)kb*64*HD;
        const float* Vtg = Vg + (size_t)kb*64*HD;
        // K: [key][d] tf32
        for (int i = tid; i < 64*32; i += 256) {
            int r = i >> 5, c4 = (i & 31) << 2;
            float4 v = *(const float4*)(Kt + (size_t)r*HD + c4);
            uint32_t* p = Ks + r*QS_STRIDE + c4;
            p[0]=f2tf32(v.x); p[1]=f2tf32(v.y); p[2]=f2tf32(v.z); p[3]=f2tf32(v.w);
        }
        // V transposed: lane-major over keys -> conflict-free STS columns
        for (int i = tid; i < 64*32; i += 256) {
            int r = i & 63;             // key
            int c4 = (i >> 6) << 2;     // dim
            float4 v = *(const float4*)(Vtg + (size_t)r*HD + c4);
            Vt[(c4+0)*VS_STRIDE + r] = f2tf32(v.x);
            Vt[(c4+1)*VS_STRIDE + r] = f2tf32(v.y);
            Vt[(c4+2)*VS_STRIDE + r] = f2tf32(v.z);
            Vt[(c4+3)*VS_STRIDE + r] = f2tf32(v.w);
        }
        __syncthreads();

        if (kb*64 > warp_rmax) continue;   // fully-masked tile for this warp

        // ---- QK^T: m16 x n64, k=128 ----
        float c[8][4];
#pragma unroll
        for (int nt = 0; nt < 8; nt++)
#pragma unroll
            for (int r = 0; r < 4; r++) c[nt][r] = 0.f;

#pragma unroll
        for (int kk = 0; kk < 16; kk++) {
            uint32_t af[4];
            af[0] = Qs[(rbase+grp  )*QS_STRIDE + kk*8 + tig];
            af[1] = Qs[(rbase+grp+8)*QS_STRIDE + kk*8 + tig];
            af[2] = Qs[(rbase+grp  )*QS_STRIDE + kk*8 + tig + 4];
            af[3] = Qs[(rbase+grp+8)*QS_STRIDE + kk*8 + tig + 4];
#pragma unroll
            for (int nt = 0; nt < 8; nt++) {
                uint32_t bf[2];
                bf[0] = Ks[(nt*8+grp)*QS_STRIDE + kk*8 + tig];
                bf[1] = Ks[(nt*8+grp)*QS_STRIDE + kk*8 + tig + 4];
                mma16n8k8(c[nt], af, bf);
            }
        }

        // ---- bias + causal + online softmax ----
        const float* brow0 = bias + ((size_t)hh*SL + rg0    )*SL + kb*64;
        const float* brow1 = bias + ((size_t)hh*SL + rg0 + 8)*SL + kb*64;
        float rm0 = -INFINITY, rm1 = -INFINITY;
#pragma unroll
        for (int nt = 0; nt < 8; nt++) {
            const int cl = nt*8 + 2*tig;
            const int cg = kb*64 + cl;
            float2 b0 = *(const float2*)(brow0 + cl);
            float2 b1 = *(const float2*)(brow1 + cl);
            c[nt][0] = (cg     > rg0    ) ? -INFINITY : c[nt][0] + b0.x;
            c[nt][1] = (cg + 1 > rg0    ) ? -INFINITY : c[nt][1] + b0.y;
            c[nt][2] = (cg     > rg0 + 8) ? -INFINITY : c[nt][2] + b1.x;
            c[nt][3] = (cg + 1 > rg0 + 8) ? -INFINITY : c[nt][3] + b1.y;
            rm0 = fmaxf(rm0, fmaxf(c[nt][0], c[nt][1]));
            rm1 = fmaxf(rm1, fmaxf(c[nt][2], c[nt][3]));
        }
        rm0 = fmaxf(rm0, __shfl_xor_sync(0xffffffffu, rm0, 1));
        rm0 = fmaxf(rm0, __shfl_xor_sync(0xffffffffu, rm0, 2));
        rm1 = fmaxf(rm1, __shfl_xor_sync(0xffffffffu, rm1, 1));
        rm1 = fmaxf(rm1, __shfl_xor_sync(0xffffffffu, rm1, 2));

        const float mn0 = fmaxf(mr0, rm0);
        const float mn1 = fmaxf(mr1, rm1);
        const float corr0 = __expf(mr0 - mn0);
        const float corr1 = __expf(mr1 - mn1);
        mr0 = mn0; mr1 = mn1;

        float rs0 = 0.f, rs1 = 0.f;
#pragma unroll
        for (int nt = 0; nt < 8; nt++) {
            uint32_t p0 = f2tf32(__expf(c[nt][0] - mn0));
            uint32_t p1 = f2tf32(__expf(c[nt][1] - mn0));
            uint32_t p2 = f2tf32(__expf(c[nt][2] - mn1));
            uint32_t p3 = f2tf32(__expf(c[nt][3] - mn1));
            rs0 += __uint_as_float(p0) + __uint_as_float(p1);
            rs1 += __uint_as_float(p2) + __uint_as_float(p3);
            const int cl = nt*8 + 2*tig;
            Ps[(rbase+grp  )*PS_STRIDE + cl    ] = p0;
            Ps[(rbase+grp  )*PS_STRIDE + cl + 1] = p1;
            Ps[(rbase+grp+8)*PS_STRIDE + cl    ] = p2;
            Ps[(rbase+grp+8)*PS_STRIDE + cl + 1] = p3;
        }
        rs0 += __shfl_xor_sync(0xffffffffu, rs0, 1);
        rs0 += __shfl_xor_sync(0xffffffffu, rs0, 2);
        rs1 += __shfl_xor_sync(0xffffffffu, rs1, 1);
        rs1 += __shfl_xor_sync(0xffffffffu, rs1, 2);
        lr0 = lr0*corr0 + rs0;
        lr1 = lr1*corr1 + rs1;
#pragma unroll
        for (int nt = 0; nt < 16; nt++) {
            o[nt][0] *= corr0; o[nt][1] *= corr0;
            o[nt][2] *= corr1; o[nt][3] *= corr1;
        }
        __syncwarp();

        // ---- P V: m16 x n128, k=64 ----
#pragma unroll
        for (int kk = 0; kk < 8; kk++) {
            uint32_t af[4];
            af[0] = Ps[(rbase+grp  )*PS_STRIDE + kk*8 + tig];
            af[1] = Ps[(rbase+grp+8)*PS_STRIDE + kk*8 + tig];
            af[2] = Ps[(rbase+grp  )*PS_STRIDE + kk*8 + tig + 4];
            af[3] = Ps[(rbase+grp+8)*PS_STRIDE + kk*8 + tig + 4];
#pragma unroll
            for (int nt = 0; nt < 16; nt++) {
                uint32_t bf[2];
                bf[0] = Vt[(nt*8+grp)*VS_STRIDE + kk*8 + tig];
                bf[1] = Vt[(nt*8+grp)*VS_STRIDE + kk*8 + tig + 4];
                mma16n8k8(o[nt], af, bf);
            }
        }
        __syncwarp();   // Ps reads done before next iteration overwrites
    }

    // ---- epilogue: normalize, write ctx [B,S,H] ----
    const float inv0 = 1.0f / lr0;
    const float inv1 = 1.0f / lr1;
    float* dst0 = g_ctx + ((size_t)bb*SL + rg0    )*HDIM + hh*HD;
    float* dst1 = g_ctx + ((size_t)bb*SL + rg0 + 8)*HDIM + hh*HD;
#pragma unroll
    for (int nt = 0; nt < 16; nt++) {
        const int d = nt*8 + 2*tig;
        *(float2*)(dst0 + d) = make_float2(o[nt][0]*inv0, o[nt][1]*inv0);
        *(float2*)(dst1 + d) = make_float2(o[nt][2]*inv1, o[nt][3]*inv1);
    }
}

// ============================================================================
extern "C" void kernel_launch(void* const* d_in, const int* in_sizes, int n_in,
                              void* d_out, int out_size)
{
    const float* hidden = (const float*)d_in[0];   // [B,S,H]
    const float* bias   = (const float*)d_in[1];   // [NH,S,S]
    // d_in[2] attention_mask: deterministic causal, applied analytically
    const float* Wqkv   = (const float*)d_in[3];   // [3H,H]
    const float* Wout   = (const float*)d_in[4];   // [H,H]
    float* out = (float*)d_out;

    cudaFuncSetAttribute(attn_mma,
                         cudaFuncAttributeMaxDynamicSharedMemorySize,
                         ATT_BYTES);

    void* ctx_ptr = nullptr;
    cudaGetSymbolAddress(&ctx_ptr, g_ctx);

    // 1) QKV projection + clamp + head-split scatter (tf32 tensor cores)
    mma_gemm_nt<1><<<dim3(N3H/128, MTOT/128), 256>>>(hidden, Wqkv, nullptr, N3H, HDIM);

    // 2) attention: tf32 tensor-core flash kernel
    attn_mma<<<dim3(SL/128, NHEAD, NB), 256, ATT_BYTES>>>(bias);

    // 3) output projection (tf32 tensor cores)
    mma_gemm_nt<0><<<dim3(HDIM/128, MTOT/128), 256>>>((const float*)ctx_ptr, Wout,
                                                      out, HDIM, HDIM);
}

// round 4
// speedup vs baseline: 3.1710x; 1.1194x over previous
#include <cuda_runtime.h>
#include <math.h>
#include <stdint.h>

#define NB 2
#define SL 2048
#define HDIM 2048
#define NHEAD 16
#define HD 128
#define MTOT (NB*SL)          // 4096
#define N3H (3*HDIM)          // 6144

#define CLIPV 8.0f
#define SM_SCALE 0.08838834764831845f   // 1/sqrt(128)

// ---- scratch (device globals; no allocation allowed) ----
__device__ uint32_t g_hid_p[(size_t)MTOT*HDIM];    // hidden, tf32 bits, k-perm
__device__ uint32_t g_wqkv_p[(size_t)N3H*HDIM];    // Wqkv,  tf32 bits, k-perm
__device__ uint32_t g_wout_p[(size_t)HDIM*HDIM];   // Wout,  tf32 bits, k-perm
__device__ uint32_t g_q[(size_t)NB*NHEAD*SL*HD];   // tf32 bits, d-perm, pre-scaled
__device__ uint32_t g_k[(size_t)NB*NHEAD*SL*HD];   // tf32 bits, d-perm
__device__ uint32_t g_v[(size_t)NB*NHEAD*SL*HD];   // tf32 bits, d-perm
__device__ uint32_t g_ctx[(size_t)MTOT*HDIM];      // tf32 bits, k-perm

__device__ __forceinline__ uint32_t f2tf32(float x) {
    uint32_t r;
    asm("cvt.rna.tf32.f32 %0, %1;" : "=r"(r) : "f"(x));
    return r;
}
__device__ __forceinline__ void mma16n8k8(float* d, const uint32_t* a,
                                          const uint32_t* b) {
    asm volatile(
        "mma.sync.aligned.m16n8k8.row.col.f32.tf32.tf32.f32 "
        "{%0,%1,%2,%3}, {%4,%5,%6,%7}, {%8,%9}, {%0,%1,%2,%3};"
        : "+f"(d[0]), "+f"(d[1]), "+f"(d[2]), "+f"(d[3])
        : "r"(a[0]), "r"(a[1]), "r"(a[2]), "r"(a[3]),
          "r"(b[0]), "r"(b[1]));
}
__device__ __forceinline__ void cp16(uint32_t dst, const void* src) {
    asm volatile("cp.async.ca.shared.global [%0], [%1], 16;"
                 :: "r"(dst), "l"(src));
}
#define CP_COMMIT() asm volatile("cp.async.commit_group;")
#define CP_WAIT0()  asm volatile("cp.async.wait_group 0;")
#define CP_WAIT1()  asm volatile("cp.async.wait_group 1;")

// within-8 pair permutation: slot = (k&3)*2 + ((k&7)>>2)
__device__ __forceinline__ int perm8(int k) {
    return (k & ~7) | ((k & 3) << 1) | ((k & 7) >> 2);
}

// ============================================================================
// prep: out[row][perm8(col)] = tf32(in[row][col]); row length 2048 (mult of 8)
// ============================================================================
__global__ void prep_perm(const float* __restrict__ in,
                          uint32_t* __restrict__ out, int n4)
{
    int t = blockIdx.x*256 + threadIdx.x;
    if (t >= n4) return;
    int idx = t*4;
    float4 v = *(const float4*)(in + idx);
    int base = idx & ~7;
    int h = (idx >> 2) & 1;
    out[base + 0 + h] = f2tf32(v.x);
    out[base + 2 + h] = f2tf32(v.y);
    out[base + 4 + h] = f2tf32(v.z);
    out[base + 6 + h] = f2tf32(v.w);
}

// ============================================================================
// tf32 NT GEMM, inputs pre-permuted tf32 bits. 128x128x32 tile, 8 warps,
// cp.async 2-stage double buffer. Smem row stride 40 words (pairs: 4g+t c-free).
// MODE 0: plain fp32 store. MODE 1: clamp, (Q: *scale), tf32, d-perm scatter
// into g_q/g_k/g_v [B,NH,S,HD].
// ============================================================================
#define GSTG 10240          // words per stage (As 5120 + Bs 5120)
#define GEMM_SMEM_BYTES (2*GSTG*4)

template<int MODE>
__global__ __launch_bounds__(256, 2)
void mma_gemm_p(const uint32_t* __restrict__ A, const uint32_t* __restrict__ Bm,
                float* __restrict__ C, int Ndim, int Kdim)
{
    extern __shared__ uint32_t gsm[];
    const int tid  = threadIdx.x;
    const int w    = tid >> 5;
    const int lane = tid & 31;
    const int grp  = lane >> 2;
    const int tig  = lane & 3;
    const int wm   = w & 3;
    const int wn   = w >> 2;

    const int k4 = (tid & 7) * 4;
    const int mb = tid >> 3;

    const uint32_t* Ag = A  + (size_t)(blockIdx.y*128 + mb)*Kdim + k4;
    const uint32_t* Bg = Bm + (size_t)(blockIdx.x*128 + mb)*Kdim + k4;
    const uint32_t sbase = (uint32_t)__cvta_generic_to_shared(gsm);

    float acc[2][8][4];
#pragma unroll
    for (int mt = 0; mt < 2; mt++)
#pragma unroll
        for (int nt = 0; nt < 8; nt++)
#pragma unroll
            for (int r = 0; r < 4; r++) acc[mt][nt][r] = 0.f;

    const int NC = Kdim / 32;

    // prologue: stage 0
    {
        uint32_t da = sbase + (0*GSTG + mb*40 + k4)*4;
        uint32_t db = da + 5120*4;
#pragma unroll
        for (int i = 0; i < 4; i++) {
            cp16(da + i*32*40*4, Ag + (size_t)i*32*Kdim);
            cp16(db + i*32*40*4, Bg + (size_t)i*32*Kdim);
        }
        CP_COMMIT();
    }

    for (int c = 0; c < NC; c++) {
        const int st = c & 1;
        if (c + 1 < NC) {
            uint32_t da = sbase + ((st^1)*GSTG + mb*40 + k4)*4;
            uint32_t db = da + 5120*4;
            const int kt = (c+1)*32;
#pragma unroll
            for (int i = 0; i < 4; i++) {
                cp16(da + i*32*40*4, Ag + kt + (size_t)i*32*Kdim);
                cp16(db + i*32*40*4, Bg + kt + (size_t)i*32*Kdim);
            }
            CP_COMMIT();
            CP_WAIT1();
        } else {
            CP_WAIT0();
        }
        __syncthreads();

        const uint32_t* As = gsm + st*GSTG;
        const uint32_t* Bs = As + 5120;
#pragma unroll
        for (int kk = 0; kk < 4; kk++) {
            uint32_t af[2][4];
#pragma unroll
            for (int mt = 0; mt < 2; mt++) {
                const int r = wm*32 + mt*16 + grp;
                uint2 a0 = *(const uint2*)&As[r*40     + kk*8 + 2*tig];
                uint2 a1 = *(const uint2*)&As[(r+8)*40 + kk*8 + 2*tig];
                af[mt][0] = a0.x; af[mt][1] = a1.x;
                af[mt][2] = a0.y; af[mt][3] = a1.y;
            }
#pragma unroll
            for (int nt = 0; nt < 8; nt++) {
                const int r = wn*64 + nt*8 + grp;
                uint2 b = *(const uint2*)&Bs[r*40 + kk*8 + 2*tig];
                uint32_t bf[2] = {b.x, b.y};
                mma16n8k8(acc[0][nt], af[0], bf);
                mma16n8k8(acc[1][nt], af[1], bf);
            }
        }
        __syncthreads();
    }

    if (MODE == 0) {
#pragma unroll
        for (int mt = 0; mt < 2; mt++) {
            const int r0 = blockIdx.y*128 + wm*32 + mt*16 + grp;
#pragma unroll
            for (int nt = 0; nt < 8; nt++) {
                const int n = blockIdx.x*128 + wn*64 + nt*8 + 2*tig;
                *(float2*)(C + (size_t)r0*Ndim + n) =
                    make_float2(acc[mt][nt][0], acc[mt][nt][1]);
                *(float2*)(C + (size_t)(r0+8)*Ndim + n) =
                    make_float2(acc[mt][nt][2], acc[mt][nt][3]);
            }
        }
    } else {
        const int nblk = blockIdx.x*128;
        const int part = nblk >> 11;
        const int hh   = (nblk & 2047) >> 7;
        uint32_t* base = (part == 0) ? g_q : (part == 1) ? g_k : g_v;
        const float sc = (part == 0) ? SM_SCALE : 1.0f;
#pragma unroll
        for (int mt = 0; mt < 2; mt++) {
#pragma unroll
            for (int rr = 0; rr < 2; rr++) {
                const int m  = blockIdx.y*128 + wm*32 + mt*16 + grp + rr*8;
                const int bb = m >> 11;
                const int ss = m & 2047;
                uint32_t* row = base + ((((size_t)bb*NHEAD) + hh)*SL + ss)*HD;
#pragma unroll
                for (int nt = 0; nt < 8; nt++) {
                    const int d = wn*64 + nt*8 + 2*tig;
                    float v0 = fminf(fmaxf(acc[mt][nt][rr*2+0], -CLIPV), CLIPV)*sc;
                    float v1 = fminf(fmaxf(acc[mt][nt][rr*2+1], -CLIPV), CLIPV)*sc;
                    row[perm8(d)]   = f2tf32(v0);
                    row[perm8(d+1)] = f2tf32(v1);
                }
            }
        }
    }
}

// ============================================================================
// Tensor-core flash attention, all-LDS.64 fragments.
// Qs [128][136] (d-perm), Ks [64][136] (rows key-perm, d-perm),
// Vt [128][72] (row=perm d, col=perm key), Ps [128][72] (col=perm key).
// ============================================================================
#define QSTR 136
#define PSTR 72
#define ATT_U32 (128*QSTR + 64*QSTR + 128*PSTR + 128*PSTR)
#define ATT_BYTES (ATT_U32*4)

__global__ __launch_bounds__(256, 1)
void attn_mma(const float* __restrict__ bias)
{
    extern __shared__ uint32_t sm[];
    uint32_t* Qs = sm;
    uint32_t* Ks = Qs + 128*QSTR;
    uint32_t* Vt = Ks + 64*QSTR;
    uint32_t* Ps = Vt + 128*PSTR;
    const uint32_t sQ = (uint32_t)__cvta_generic_to_shared(Qs);
    const uint32_t sK = (uint32_t)__cvta_generic_to_shared(Ks);

    const int qb = blockIdx.x;
    const int hh = blockIdx.y;
    const int bb = blockIdx.z;
    const int tid  = threadIdx.x;
    const int w    = tid >> 5;
    const int lane = tid & 31;
    const int grp  = lane >> 2;
    const int tig  = lane & 3;
    const int rbase = w*16;

    const size_t bhs = ((size_t)bb*NHEAD + hh)*SL;
    const uint32_t* Qg = g_q + (bhs + (size_t)qb*128)*HD;
    const uint32_t* Kg = g_k + bhs*HD;
    const uint32_t* Vg = g_v + bhs*HD;

    // Q tile via cp.async (pre-scaled tf32 perm-d)
    for (int cid = tid; cid < 4096; cid += 256) {
        int r = cid >> 5, c4 = (cid & 31) << 2;
        cp16(sQ + (r*QSTR + c4)*4, Qg + (size_t)r*HD + c4);
    }
    CP_COMMIT();

    float o[16][4];
#pragma unroll
    for (int nt = 0; nt < 16; nt++)
#pragma unroll
        for (int r = 0; r < 4; r++) o[nt][r] = 0.f;
    float mr0 = -INFINITY, mr1 = -INFINITY, lr0 = 0.f, lr1 = 0.f;

    const int rg0 = qb*128 + rbase + grp;
    const int warp_rmax = qb*128 + rbase + 15;
    const int kb_max = 2*qb + 1;

    for (int kb = 0; kb <= kb_max; kb++) {
        __syncthreads();   // prev PV reads done
        const uint32_t* Kt  = Kg + (size_t)kb*64*HD;
        const uint32_t* Vtg = Vg + (size_t)kb*64*HD;
        // K tile: cp.async, rows stored key-permuted
        for (int cid = tid; cid < 2048; cid += 256) {
            int r = cid >> 5, c4 = (cid & 31) << 2;
            cp16(sK + (perm8(r)*QSTR + c4)*4, Kt + (size_t)r*HD + c4);
        }
        // V transpose (overlaps K cp.async): col = perm key
        for (int i = tid; i < 2048; i += 256) {
            int r = i & 63;
            int c4 = (i >> 6) << 2;
            uint4 v = *(const uint4*)(Vtg + (size_t)r*HD + c4);
            int pr = perm8(r);
            Vt[(c4+0)*PSTR + pr] = v.x;
            Vt[(c4+1)*PSTR + pr] = v.y;
            Vt[(c4+2)*PSTR + pr] = v.z;
            Vt[(c4+3)*PSTR + pr] = v.w;
        }
        CP_COMMIT();
        CP_WAIT0();
        __syncthreads();

        if (kb*64 > warp_rmax) continue;

        // ---- QK^T ----
        float c[8][4];
#pragma unroll
        for (int nt = 0; nt < 8; nt++)
#pragma unroll
            for (int r = 0; r < 4; r++) c[nt][r] = 0.f;

#pragma unroll
        for (int kk = 0; kk < 16; kk++) {
            uint2 qa = *(const uint2*)&Qs[(rbase+grp  )*QSTR + kk*8 + 2*tig];
            uint2 qbv= *(const uint2*)&Qs[(rbase+grp+8)*QSTR + kk*8 + 2*tig];
            uint32_t af[4] = {qa.x, qbv.x, qa.y, qbv.y};
#pragma unroll
            for (int nt = 0; nt < 8; nt++) {
                uint2 kf = *(const uint2*)&Ks[(nt*8+grp)*QSTR + kk*8 + 2*tig];
                uint32_t bf[2] = {kf.x, kf.y};
                mma16n8k8(c[nt], af, bf);
            }
        }

        // ---- bias + causal + online softmax ----
        // score col slots 2tig,2tig+1 <-> orig keys (tig, tig+4)
        const float* br0 = bias + ((size_t)hh*SL + rg0)*SL + kb*64;
        const float* br1 = br0 + (size_t)8*SL;
        float rm0 = -INFINITY, rm1 = -INFINITY;
#pragma unroll
        for (int nt = 0; nt < 8; nt++) {
            const int k0 = nt*8 + tig;
            const int cg = kb*64 + k0;
            float b0 = br0[k0], b1 = br0[k0+4];
            float b2 = br1[k0], b3 = br1[k0+4];
            c[nt][0] = (cg     > rg0    ) ? -INFINITY : c[nt][0] + b0;
            c[nt][1] = (cg + 4 > rg0    ) ? -INFINITY : c[nt][1] + b1;
            c[nt][2] = (cg     > rg0 + 8) ? -INFINITY : c[nt][2] + b2;
            c[nt][3] = (cg + 4 > rg0 + 8) ? -INFINITY : c[nt][3] + b3;
            rm0 = fmaxf(rm0, fmaxf(c[nt][0], c[nt][1]));
            rm1 = fmaxf(rm1, fmaxf(c[nt][2], c[nt][3]));
        }
        rm0 = fmaxf(rm0, __shfl_xor_sync(0xffffffffu, rm0, 1));
        rm0 = fmaxf(rm0, __shfl_xor_sync(0xffffffffu, rm0, 2));
        rm1 = fmaxf(rm1, __shfl_xor_sync(0xffffffffu, rm1, 1));
        rm1 = fmaxf(rm1, __shfl_xor_sync(0xffffffffu, rm1, 2));

        const float mn0 = fmaxf(mr0, rm0);
        const float mn1 = fmaxf(mr1, rm1);
        const float corr0 = __expf(mr0 - mn0);
        const float corr1 = __expf(mr1 - mn1);
        mr0 = mn0; mr1 = mn1;

        float rs0 = 0.f, rs1 = 0.f;
#pragma unroll
        for (int nt = 0; nt < 8; nt++) {
            uint32_t p0 = f2tf32(__expf(c[nt][0] - mn0));
            uint32_t p1 = f2tf32(__expf(c[nt][1] - mn0));
            uint32_t p2 = f2tf32(__expf(c[nt][2] - mn1));
            uint32_t p3 = f2tf32(__expf(c[nt][3] - mn1));
            rs0 += __uint_as_float(p0) + __uint_as_float(p1);
            rs1 += __uint_as_float(p2) + __uint_as_float(p3);
            uint2 w0 = make_uint2(p0, p1);
            uint2 w1 = make_uint2(p2, p3);
            *(uint2*)&Ps[(rbase+grp  )*PSTR + nt*8 + 2*tig] = w0;
            *(uint2*)&Ps[(rbase+grp+8)*PSTR + nt*8 + 2*tig] = w1;
        }
        rs0 += __shfl_xor_sync(0xffffffffu, rs0, 1);
        rs0 += __shfl_xor_sync(0xffffffffu, rs0, 2);
        rs1 += __shfl_xor_sync(0xffffffffu, rs1, 1);
        rs1 += __shfl_xor_sync(0xffffffffu, rs1, 2);
        lr0 = lr0*corr0 + rs0;
        lr1 = lr1*corr1 + rs1;
#pragma unroll
        for (int nt = 0; nt < 16; nt++) {
            o[nt][0] *= corr0; o[nt][1] *= corr0;
            o[nt][2] *= corr1; o[nt][3] *= corr1;
        }
        __syncwarp();

        // ---- P V ----
#pragma unroll
        for (int kk = 0; kk < 8; kk++) {
            uint2 pa = *(const uint2*)&Ps[(rbase+grp  )*PSTR + kk*8 + 2*tig];
            uint2 pb = *(const uint2*)&Ps[(rbase+grp+8)*PSTR + kk*8 + 2*tig];
            uint32_t af[4] = {pa.x, pb.x, pa.y, pb.y};
#pragma unroll
            for (int nt = 0; nt < 16; nt++) {
                uint2 vb = *(const uint2*)&Vt[(nt*8+grp)*PSTR + kk*8 + 2*tig];
                uint32_t bf[2] = {vb.x, vb.y};
                mma16n8k8(o[nt], af, bf);
            }
        }
        __syncwarp();
    }

    // epilogue: normalize, tf32, write ctx (H already in permuted slot order)
    const float inv0 = 1.0f / lr0;
    const float inv1 = 1.0f / lr1;
    uint32_t* dst0 = g_ctx + ((size_t)bb*SL + rg0    )*HDIM + hh*HD;
    uint32_t* dst1 = g_ctx + ((size_t)bb*SL + rg0 + 8)*HDIM + hh*HD;
#pragma unroll
    for (int nt = 0; nt < 16; nt++) {
        const int d = nt*8 + 2*tig;
        *(uint2*)(dst0 + d) = make_uint2(f2tf32(o[nt][0]*inv0),
                                         f2tf32(o[nt][1]*inv0));
        *(uint2*)(dst1 + d) = make_uint2(f2tf32(o[nt][2]*inv1),
                                         f2tf32(o[nt][3]*inv1));
    }
}

// ============================================================================
extern "C" void kernel_launch(void* const* d_in, const int* in_sizes, int n_in,
                              void* d_out, int out_size)
{
    const float* hidden = (const float*)d_in[0];   // [B,S,H]
    const float* bias   = (const float*)d_in[1];   // [NH,S,S]
    // d_in[2] attention_mask: deterministic causal, applied analytically
    const float* Wqkv   = (const float*)d_in[3];   // [3H,H]
    const float* Wout   = (const float*)d_in[4];   // [H,H]
    float* out = (float*)d_out;

    cudaFuncSetAttribute(attn_mma,
                         cudaFuncAttributeMaxDynamicSharedMemorySize, ATT_BYTES);
    cudaFuncSetAttribute(mma_gemm_p<0>,
                         cudaFuncAttributeMaxDynamicSharedMemorySize, GEMM_SMEM_BYTES);
    cudaFuncSetAttribute(mma_gemm_p<1>,
                         cudaFuncAttributeMaxDynamicSharedMemorySize, GEMM_SMEM_BYTES);

    void *hidp, *wqkvp, *woutp, *ctxp;
    cudaGetSymbolAddress(&hidp,  g_hid_p);
    cudaGetSymbolAddress(&wqkvp, g_wqkv_p);
    cudaGetSymbolAddress(&woutp, g_wout_p);
    cudaGetSymbolAddress(&ctxp,  g_ctx);

    // 0) permute + tf32-convert inputs
    prep_perm<<<(MTOT*HDIM/4 + 255)/256, 256>>>(hidden, (uint32_t*)hidp, MTOT*HDIM/4);
    prep_perm<<<(N3H*HDIM/4  + 255)/256, 256>>>(Wqkv,   (uint32_t*)wqkvp, N3H*HDIM/4);
    prep_perm<<<(HDIM*HDIM/4 + 255)/256, 256>>>(Wout,   (uint32_t*)woutp, HDIM*HDIM/4);

    // 1) QKV projection + clamp + scale(Q) + head-split scatter
    mma_gemm_p<1><<<dim3(N3H/128, MTOT/128), 256, GEMM_SMEM_BYTES>>>(
        (const uint32_t*)hidp, (const uint32_t*)wqkvp, nullptr, N3H, HDIM);

    // 2) attention
    attn_mma<<<dim3(SL/128, NHEAD, NB), 256, ATT_BYTES>>>(bias);

    // 3) output projection
    mma_gemm_p<0><<<dim3(HDIM/128, MTOT/128), 256, GEMM_SMEM_BYTES>>>(
        (const uint32_t*)ctxp, (const uint32_t*)woutp, out, HDIM, HDIM);
}

// round 6
// speedup vs baseline: 3.4026x; 1.0730x over previous
#include <cuda_runtime.h>
#include <math.h>
#include <stdint.h>

#define NB 2
#define SL 2048
#define HDIM 2048
#define NHEAD 16
#define HD 128
#define MTOT (NB*SL)          // 4096
#define N3H (3*HDIM)          // 6144

#define CLIPV 8.0f
#define SM_SCALE 0.08838834764831845f   // 1/sqrt(128)

// ---- scratch (device globals; no allocation allowed) ----
__device__ uint32_t g_hid_p[(size_t)MTOT*HDIM];    // hidden, tf32 bits, k-perm
__device__ uint32_t g_wqkv_p[(size_t)N3H*HDIM];    // Wqkv,  tf32 bits, k-perm
__device__ uint32_t g_wout_p[(size_t)HDIM*HDIM];   // Wout,  tf32 bits, k-perm
__device__ uint32_t g_q[(size_t)NB*NHEAD*SL*HD];   // [B,NH,S,d-slot], pre-scaled
__device__ uint32_t g_k[(size_t)NB*NHEAD*SL*HD];   // [B,NH,S,d-slot]
__device__ uint32_t g_vT[(size_t)NB*NHEAD*HD*SL];  // [B,NH,d-slot,s-keyperm]
__device__ uint32_t g_ctx[(size_t)MTOT*HDIM];      // tf32 bits, k-perm

__device__ __forceinline__ uint32_t f2tf32(float x) {
    uint32_t r;
    asm("cvt.rna.tf32.f32 %0, %1;" : "=r"(r) : "f"(x));
    return r;
}
__device__ __forceinline__ void mma16n8k8(float* d, const uint32_t* a,
                                          const uint32_t* b) {
    asm volatile(
        "mma.sync.aligned.m16n8k8.row.col.f32.tf32.tf32.f32 "
        "{%0,%1,%2,%3}, {%4,%5,%6,%7}, {%8,%9}, {%0,%1,%2,%3};"
        : "+f"(d[0]), "+f"(d[1]), "+f"(d[2]), "+f"(d[3])
        : "r"(a[0]), "r"(a[1]), "r"(a[2]), "r"(a[3]),
          "r"(b[0]), "r"(b[1]));
}
__device__ __forceinline__ void cp16(uint32_t dst, const void* src) {
    asm volatile("cp.async.ca.shared.global [%0], [%1], 16;"
                 :: "r"(dst), "l"(src));
}
#define CP_COMMIT() asm volatile("cp.async.commit_group;")
#define CP_WAIT0()  asm volatile("cp.async.wait_group 0;")
#define CP_WAIT1()  asm volatile("cp.async.wait_group 1;")

__device__ __forceinline__ uint32_t smem_u32(const void* p) {
    uint32_t a;
    asm("{ .reg .u64 t; cvta.to.shared.u64 t, %1; cvt.u32.u64 %0, t; }"
        : "=r"(a) : "l"(p));
    return a;
}

// within-8 pair permutation: slot = (k&3)*2 + ((k&7)>>2)
__device__ __forceinline__ int perm8(int k) {
    return (k & ~7) | ((k & 3) << 1) | ((k & 7) >> 2);
}

// ============================================================================
// prep: out[row][perm8(col)] = tf32(in[row][col])
// ============================================================================
__global__ void prep_perm(const float* __restrict__ in,
                          uint32_t* __restrict__ out, int n4)
{
    int t = blockIdx.x*256 + threadIdx.x;
    if (t >= n4) return;
    int idx = t*4;
    float4 v = *(const float4*)(in + idx);
    int base = idx & ~7;
    int h = (idx >> 2) & 1;
    out[base + 0 + h] = f2tf32(v.x);
    out[base + 2 + h] = f2tf32(v.y);
    out[base + 4 + h] = f2tf32(v.z);
    out[base + 6 + h] = f2tf32(v.w);
}

// ============================================================================
// tf32 NT GEMM (mma.sync), pre-permuted inputs, 128x128x32, cp.async 2-stage.
// MODE 0: plain fp32 store. MODE 1: clamp, scale(Q), tf32, scatter:
//   Q/K -> [B,NH,S,d-slot];  V -> g_vT [B,NH,d-slot,s-keyperm] (transposed).
// ============================================================================
#define GSTG 10240          // words per stage (As 5120 + Bs 5120)
#define GEMM_SMEM_BYTES (2*GSTG*4)

template<int MODE>
__global__ __launch_bounds__(256, 2)
void mma_gemm_p(const uint32_t* __restrict__ A, const uint32_t* __restrict__ Bm,
                float* __restrict__ C, int Ndim, int Kdim)
{
    extern __shared__ uint32_t gsm[];
    const int tid  = threadIdx.x;
    const int lane = tid & 31;
    const int grp  = lane >> 2;
    const int tig  = lane & 3;
    const int wm   = (tid >> 5) & 3;
    const int wn   = tid >> 7;

    const int k4 = (tid & 7) * 4;
    const int mb = tid >> 3;

    const uint32_t* Ag = A  + (size_t)(blockIdx.y*128 + mb)*Kdim + k4;
    const uint32_t* Bg = Bm + (size_t)(blockIdx.x*128 + mb)*Kdim + k4;
    const uint32_t sbase = smem_u32(gsm);

    float acc[2][8][4];
#pragma unroll
    for (int mt = 0; mt < 2; mt++)
#pragma unroll
        for (int nt = 0; nt < 8; nt++)
#pragma unroll
            for (int r = 0; r < 4; r++) acc[mt][nt][r] = 0.f;

    const int NC = Kdim / 32;

    {
        uint32_t da = sbase + (mb*40 + k4)*4;
        uint32_t db = da + 5120*4;
#pragma unroll
        for (int i = 0; i < 4; i++) {
            cp16(da + i*32*40*4, Ag + (size_t)i*32*Kdim);
            cp16(db + i*32*40*4, Bg + (size_t)i*32*Kdim);
        }
        CP_COMMIT();
    }

    for (int c = 0; c < NC; c++) {
        const int st = c & 1;
        if (c + 1 < NC) {
            uint32_t da = sbase + ((st^1)*GSTG + mb*40 + k4)*4;
            uint32_t db = da + 5120*4;
            const int kt = (c+1)*32;
#pragma unroll
            for (int i = 0; i < 4; i++) {
                cp16(da + i*32*40*4, Ag + kt + (size_t)i*32*Kdim);
                cp16(db + i*32*40*4, Bg + kt + (size_t)i*32*Kdim);
            }
            CP_COMMIT();
            CP_WAIT1();
        } else {
            CP_WAIT0();
        }
        __syncthreads();

        const uint32_t* As = gsm + st*GSTG;
        const uint32_t* Bs = As + 5120;
#pragma unroll
        for (int kk = 0; kk < 4; kk++) {
            uint32_t af[2][4];
#pragma unroll
            for (int mt = 0; mt < 2; mt++) {
                const int r = wm*32 + mt*16 + grp;
                uint2 a0 = *(const uint2*)&As[r*40     + kk*8 + 2*tig];
                uint2 a1 = *(const uint2*)&As[(r+8)*40 + kk*8 + 2*tig];
                af[mt][0] = a0.x; af[mt][1] = a1.x;
                af[mt][2] = a0.y; af[mt][3] = a1.y;
            }
#pragma unroll
            for (int nt = 0; nt < 8; nt++) {
                const int r = wn*64 + nt*8 + grp;
                uint2 b = *(const uint2*)&Bs[r*40 + kk*8 + 2*tig];
                uint32_t bf[2] = {b.x, b.y};
                mma16n8k8(acc[0][nt], af[0], bf);
                mma16n8k8(acc[1][nt], af[1], bf);
            }
        }
        __syncthreads();
    }

    if (MODE == 0) {
#pragma unroll
        for (int mt = 0; mt < 2; mt++) {
            const int r0 = blockIdx.y*128 + wm*32 + mt*16 + grp;
#pragma unroll
            for (int nt = 0; nt < 8; nt++) {
                const int n = blockIdx.x*128 + wn*64 + nt*8 + 2*tig;
                *(float2*)(C + (size_t)r0*Ndim + n) =
                    make_float2(acc[mt][nt][0], acc[mt][nt][1]);
                *(float2*)(C + (size_t)(r0+8)*Ndim + n) =
                    make_float2(acc[mt][nt][2], acc[mt][nt][3]);
            }
        }
    } else {
        const int nblk = blockIdx.x*128;
        const int part = nblk >> 11;            // 0:Q 1:K 2:V
        const int hh   = (nblk & 2047) >> 7;
        if (part < 2) {
            uint32_t* base = (part == 0) ? g_q : g_k;
            const float sc = (part == 0) ? SM_SCALE : 1.0f;
#pragma unroll
            for (int mt = 0; mt < 2; mt++) {
#pragma unroll
                for (int rr = 0; rr < 2; rr++) {
                    const int m  = blockIdx.y*128 + wm*32 + mt*16 + grp + rr*8;
                    const int bb = m >> 11;
                    const int ss = m & 2047;
                    uint32_t* row = base + ((((size_t)bb*NHEAD) + hh)*SL + ss)*HD;
#pragma unroll
                    for (int nt = 0; nt < 8; nt++) {
                        const int d = wn*64 + nt*8 + 2*tig;
                        float v0 = fminf(fmaxf(acc[mt][nt][rr*2+0], -CLIPV), CLIPV)*sc;
                        float v1 = fminf(fmaxf(acc[mt][nt][rr*2+1], -CLIPV), CLIPV)*sc;
                        row[perm8(d)]   = f2tf32(v0);
                        row[perm8(d+1)] = f2tf32(v1);
                    }
                }
            }
        } else {
            // V: transposed store, key-permuted column
#pragma unroll
            for (int mt = 0; mt < 2; mt++) {
#pragma unroll
                for (int rr = 0; rr < 2; rr++) {
                    const int m  = blockIdx.y*128 + wm*32 + mt*16 + grp + rr*8;
                    const int bb = m >> 11;
                    const int ss = m & 2047;
                    const int scol = perm8(ss);
                    uint32_t* vb = g_vT + (((size_t)bb*NHEAD + hh)*HD)*SL + scol;
#pragma unroll
                    for (int nt = 0; nt < 8; nt++) {
                        const int d = wn*64 + nt*8 + 2*tig;
                        float v0 = fminf(fmaxf(acc[mt][nt][rr*2+0], -CLIPV), CLIPV);
                        float v1 = fminf(fmaxf(acc[mt][nt][rr*2+1], -CLIPV), CLIPV);
                        vb[(size_t)perm8(d)  *SL] = f2tf32(v0);
                        vb[(size_t)perm8(d+1)*SL] = f2tf32(v1);
                    }
                }
            }
        }
    }
}

// ============================================================================
// Tensor-core flash attention v2: Q fragments in registers, double-buffered
// cp.async K+V tiles (V pre-transposed in gmem), BM=128, BN=64, 8 warps.
// ============================================================================
#define KSTR 136
#define VSTR 72
#define PSTR 72
#define KS_SZ (64*KSTR)
#define VT_SZ (128*VSTR)
#define ATT_U32 (2*KS_SZ + 2*VT_SZ + 128*PSTR)
#define ATT_BYTES (ATT_U32*4)

__global__ __launch_bounds__(256, 1)
void attn_mma(const float* __restrict__ bias)
{
    extern __shared__ uint32_t sm[];
    uint32_t* KsB = sm;                 // [2][64][KSTR]
    uint32_t* VtB = sm + 2*KS_SZ;       // [2][128][VSTR]
    uint32_t* Ps  = sm + 2*KS_SZ + 2*VT_SZ;   // [128][PSTR]
    const uint32_t sKs = smem_u32(KsB);
    const uint32_t sVt = smem_u32(VtB);

    const int qb = blockIdx.x;
    const int hh = blockIdx.y;
    const int bb = blockIdx.z;
    const int tid  = threadIdx.x;
    const int w    = tid >> 5;
    const int lane = tid & 31;
    const int grp  = lane >> 2;
    const int tig  = lane & 3;
    const int rbase = w*16;

    const size_t bhs = ((size_t)bb*NHEAD + hh)*SL;
    const uint32_t* Qg = g_q + (bhs + (size_t)qb*128)*HD;
    const uint32_t* Kg = g_k + bhs*HD;
    const uint32_t* Vg = g_vT + bhs*HD;      // (bb*NH+hh)*HD*SL

    auto load_tile = [&](int buf, int kb) {
        const uint32_t* Kt = Kg + (size_t)kb*64*HD;
        const uint32_t dK = sKs + buf*KS_SZ*4;
#pragma unroll
        for (int p = 0; p < 8; p++) {
            int i = tid + p*256;
            int r = i >> 5, c4 = (i & 31) << 2;
            cp16(dK + (perm8(r)*KSTR + c4)*4, Kt + (size_t)r*HD + c4);
        }
        const uint32_t* Vt0 = Vg + (size_t)kb*64;
        const uint32_t dV = sVt + buf*VT_SZ*4;
#pragma unroll
        for (int p = 0; p < 8; p++) {
            int i = tid + p*256;
            int d = i >> 4, c4 = (i & 15) << 2;
            cp16(dV + (d*VSTR + c4)*4, Vt0 + (size_t)d*SL + c4);
        }
    };

    // prologue: tile 0 in flight
    load_tile(0, 0);
    CP_COMMIT();

    // Q fragments -> registers (reused across all key tiles)
    uint2 qA[16], qB[16];
    {
        const uint32_t* q0 = Qg + (size_t)(rbase + grp)*HD + 2*tig;
        const uint32_t* q1 = q0 + 8*HD;
#pragma unroll
        for (int kk = 0; kk < 16; kk++) {
            qA[kk] = *(const uint2*)(q0 + kk*8);
            qB[kk] = *(const uint2*)(q1 + kk*8);
        }
    }

    float o[16][4];
#pragma unroll
    for (int nt = 0; nt < 16; nt++)
#pragma unroll
        for (int r = 0; r < 4; r++) o[nt][r] = 0.f;
    float mr0 = -INFINITY, mr1 = -INFINITY, lr0 = 0.f, lr1 = 0.f;

    const int rg0 = qb*128 + rbase + grp;
    const int warp_rmax = qb*128 + rbase + 15;
    const int kb_max = 2*qb + 1;

    for (int kb = 0; kb <= kb_max; kb++) {
        const int buf = kb & 1;
        if (kb < kb_max) {
            load_tile(buf ^ 1, kb + 1);
            CP_COMMIT();
            CP_WAIT1();
        } else {
            CP_WAIT0();
        }
        __syncthreads();          // tile kb visible to all warps

        if (kb*64 <= warp_rmax) {
            const uint32_t* Ks = KsB + buf*KS_SZ;
            const uint32_t* Vt = VtB + buf*VT_SZ;

            // ---- QK^T: m16 x n64, k=128 (Q from regs) ----
            float c[8][4];
#pragma unroll
            for (int nt = 0; nt < 8; nt++)
#pragma unroll
                for (int r = 0; r < 4; r++) c[nt][r] = 0.f;

#pragma unroll
            for (int kk = 0; kk < 16; kk++) {
                uint32_t af[4] = {qA[kk].x, qB[kk].x, qA[kk].y, qB[kk].y};
#pragma unroll
                for (int nt = 0; nt < 8; nt++) {
                    uint2 kf = *(const uint2*)&Ks[(nt*8+grp)*KSTR + kk*8 + 2*tig];
                    uint32_t bf[2] = {kf.x, kf.y};
                    mma16n8k8(c[nt], af, bf);
                }
            }

            // ---- bias + causal + online softmax ----
            const float* br0 = bias + ((size_t)hh*SL + rg0)*SL + kb*64;
            const float* br1 = br0 + (size_t)8*SL;
            float rm0 = -INFINITY, rm1 = -INFINITY;
#pragma unroll
            for (int nt = 0; nt < 8; nt++) {
                const int k0 = nt*8 + tig;
                const int cg = kb*64 + k0;
                float b0 = br0[k0], b1 = br0[k0+4];
                float b2 = br1[k0], b3 = br1[k0+4];
                c[nt][0] = (cg     > rg0    ) ? -INFINITY : c[nt][0] + b0;
                c[nt][1] = (cg + 4 > rg0    ) ? -INFINITY : c[nt][1] + b1;
                c[nt][2] = (cg     > rg0 + 8) ? -INFINITY : c[nt][2] + b2;
                c[nt][3] = (cg + 4 > rg0 + 8) ? -INFINITY : c[nt][3] + b3;
                rm0 = fmaxf(rm0, fmaxf(c[nt][0], c[nt][1]));
                rm1 = fmaxf(rm1, fmaxf(c[nt][2], c[nt][3]));
            }
            rm0 = fmaxf(rm0, __shfl_xor_sync(0xffffffffu, rm0, 1));
            rm0 = fmaxf(rm0, __shfl_xor_sync(0xffffffffu, rm0, 2));
            rm1 = fmaxf(rm1, __shfl_xor_sync(0xffffffffu, rm1, 1));
            rm1 = fmaxf(rm1, __shfl_xor_sync(0xffffffffu, rm1, 2));

            const float mn0 = fmaxf(mr0, rm0);
            const float mn1 = fmaxf(mr1, rm1);
            const float corr0 = __expf(mr0 - mn0);
            const float corr1 = __expf(mr1 - mn1);
            mr0 = mn0; mr1 = mn1;

            float rs0 = 0.f, rs1 = 0.f;
#pragma unroll
            for (int nt = 0; nt < 8; nt++) {
                uint32_t p0 = f2tf32(__expf(c[nt][0] - mn0));
                uint32_t p1 = f2tf32(__expf(c[nt][1] - mn0));
                uint32_t p2 = f2tf32(__expf(c[nt][2] - mn1));
                uint32_t p3 = f2tf32(__expf(c[nt][3] - mn1));
                rs0 += __uint_as_float(p0) + __uint_as_float(p1);
                rs1 += __uint_as_float(p2) + __uint_as_float(p3);
                *(uint2*)&Ps[(rbase+grp  )*PSTR + nt*8 + 2*tig] = make_uint2(p0, p1);
                *(uint2*)&Ps[(rbase+grp+8)*PSTR + nt*8 + 2*tig] = make_uint2(p2, p3);
            }
            rs0 += __shfl_xor_sync(0xffffffffu, rs0, 1);
            rs0 += __shfl_xor_sync(0xffffffffu, rs0, 2);
            rs1 += __shfl_xor_sync(0xffffffffu, rs1, 1);
            rs1 += __shfl_xor_sync(0xffffffffu, rs1, 2);
            lr0 = lr0*corr0 + rs0;
            lr1 = lr1*corr1 + rs1;
#pragma unroll
            for (int nt = 0; nt < 16; nt++) {
                o[nt][0] *= corr0; o[nt][1] *= corr0;
                o[nt][2] *= corr1; o[nt][3] *= corr1;
            }
            __syncwarp();

            // ---- P V: m16 x n128, k=64 ----
#pragma unroll
            for (int kk = 0; kk < 8; kk++) {
                uint2 pa = *(const uint2*)&Ps[(rbase+grp  )*PSTR + kk*8 + 2*tig];
                uint2 pb = *(const uint2*)&Ps[(rbase+grp+8)*PSTR + kk*8 + 2*tig];
                uint32_t af[4] = {pa.x, pb.x, pa.y, pb.y};
#pragma unroll
                for (int nt = 0; nt < 16; nt++) {
                    uint2 vb = *(const uint2*)&Vt[(nt*8+grp)*VSTR + kk*8 + 2*tig];
                    uint32_t bf[2] = {vb.x, vb.y};
                    mma16n8k8(o[nt], af, bf);
                }
            }
            __syncwarp();
        }

        __syncthreads();          // everyone done with buf before it refills
    }

    // epilogue: normalize, tf32, write ctx (slot order matches g_wout_p perm)
    const float inv0 = 1.0f / lr0;
    const float inv1 = 1.0f / lr1;
    uint32_t* dst0 = g_ctx + ((size_t)bb*SL + rg0    )*HDIM + hh*HD;
    uint32_t* dst1 = g_ctx + ((size_t)bb*SL + rg0 + 8)*HDIM + hh*HD;
#pragma unroll
    for (int nt = 0; nt < 16; nt++) {
        const int d = nt*8 + 2*tig;
        *(uint2*)(dst0 + d) = make_uint2(f2tf32(o[nt][0]*inv0),
                                         f2tf32(o[nt][1]*inv0));
        *(uint2*)(dst1 + d) = make_uint2(f2tf32(o[nt][2]*inv1),
                                         f2tf32(o[nt][3]*inv1));
    }
}

// ============================================================================
extern "C" void kernel_launch(void* const* d_in, const int* in_sizes, int n_in,
                              void* d_out, int out_size)
{
    const float* hidden = (const float*)d_in[0];   // [B,S,H]
    const float* bias   = (const float*)d_in[1];   // [NH,S,S]
    // d_in[2] attention_mask: deterministic causal, applied analytically
    const float* Wqkv   = (const float*)d_in[3];   // [3H,H]
    const float* Wout   = (const float*)d_in[4];   // [H,H]
    float* out = (float*)d_out;

    cudaFuncSetAttribute(attn_mma,
                         cudaFuncAttributeMaxDynamicSharedMemorySize, ATT_BYTES);
    cudaFuncSetAttribute(mma_gemm_p<0>,
                         cudaFuncAttributeMaxDynamicSharedMemorySize, GEMM_SMEM_BYTES);
    cudaFuncSetAttribute(mma_gemm_p<1>,
                         cudaFuncAttributeMaxDynamicSharedMemorySize, GEMM_SMEM_BYTES);

    void *hidp, *wqkvp, *woutp, *ctxp;
    cudaGetSymbolAddress(&hidp,  g_hid_p);
    cudaGetSymbolAddress(&wqkvp, g_wqkv_p);
    cudaGetSymbolAddress(&woutp, g_wout_p);
    cudaGetSymbolAddress(&ctxp,  g_ctx);

    // 0) permute + tf32-convert inputs
    prep_perm<<<(MTOT*HDIM/4 + 255)/256, 256>>>(hidden, (uint32_t*)hidp, MTOT*HDIM/4);
    prep_perm<<<(N3H*HDIM/4  + 255)/256, 256>>>(Wqkv,   (uint32_t*)wqkvp, N3H*HDIM/4);
    prep_perm<<<(HDIM*HDIM/4 + 255)/256, 256>>>(Wout,   (uint32_t*)woutp, HDIM*HDIM/4);

    // 1) QKV projection + clamp + scale(Q) + scatter (V transposed)
    mma_gemm_p<1><<<dim3(N3H/128, MTOT/128), 256, GEMM_SMEM_BYTES>>>(
        (const uint32_t*)hidp, (const uint32_t*)wqkvp, nullptr, N3H, HDIM);

    // 2) attention (double-buffered tensor-core flash)
    attn_mma<<<dim3(SL/128, NHEAD, NB), 256, ATT_BYTES>>>(bias);

    // 3) output projection
    mma_gemm_p<0><<<dim3(HDIM/128, MTOT/128), 256, GEMM_SMEM_BYTES>>>(
        (const uint32_t*)ctxp, (const uint32_t*)woutp, out, HDIM, HDIM);
}